// round 14
// baseline (speedup 1.0000x reference)
#include <cuda_runtime.h>
#include <cstdint>

#define NN 50000
#define EE 400000
#define DD 128
#define HH 4
#define DHh 32
#define TT 3
#define RR 6
#define LLn 2
#define EPSV 1e-5f

// edge kernel: 8 warps/block, warp = 8 edges (all 4 heads); block = 64 edges
#define EDGE_GRID (EE / 64)

// ---------------- static scratch (no allocations allowed) ----------------
__device__ float g_k[NN * DD];
__device__ float g_q[NN * DD];
__device__ float g_v[NN * DD];
__device__ float g_agg[NN * DD];
__device__ float g_ha[NN * DD];
__device__ float g_o0[NN * DD];
__device__ float g_o1[NN * DD];
__device__ float g_den[NN * HH];

__device__ __forceinline__ uint32_t to_tf32(float v) {
    uint32_t r;
    asm("cvt.rna.tf32.f32 %0, %1;" : "=r"(r) : "f"(v));
    return r;
}

__device__ __forceinline__ void mma_tf32(float* c, uint32_t a0, uint32_t a1,
                                         uint32_t a2, uint32_t a3,
                                         uint32_t b0, uint32_t b1) {
    asm volatile(
        "mma.sync.aligned.m16n8k8.row.col.f32.tf32.tf32.f32 "
        "{%0,%1,%2,%3}, {%4,%5,%6,%7}, {%8,%9}, {%0,%1,%2,%3};"
        : "+f"(c[0]), "+f"(c[1]), "+f"(c[2]), "+f"(c[3])
        : "r"(a0), "r"(a1), "r"(a2), "r"(a3), "r"(b0), "r"(b1));
}

// ---------------- init: zero g_agg + g_den ----------------
__global__ void __launch_bounds__(256) init_kernel() {
    int i = blockIdx.x * blockDim.x + threadIdx.x;
    if (i < NN * DD / 4)
        ((float4*)g_agg)[i] = make_float4(0.f, 0.f, 0.f, 0.f);
    if (i < NN * HH)
        g_den[i] = 0.f;
}

// ---------------- tf32 tensor-core typed linear (unchanged from R10) ------
#define XP 132
__global__ void __launch_bounds__(256) typed_linear_kernel(
    const float* __restrict__ xext, int in_sel,
    const int* __restrict__ ntype,
    const float* __restrict__ W0, const float* __restrict__ W1,
    const float* __restrict__ W2, int nmat)
{
    const float* x = (in_sel == 0) ? xext : (in_sel == 1 ? (const float*)g_agg
                                                         : (const float*)g_o0);
    __shared__ float xs[64][XP];
    __shared__ int ts[64];
    int tid = threadIdx.x;
    int row0 = blockIdx.x * 64;

    for (int i = tid; i < 64 * 32; i += 256) {
        int r = i >> 5, c4 = i & 31;
        int gr = row0 + r;
        float4 val = make_float4(0.f, 0.f, 0.f, 0.f);
        if (gr < NN) {
            val = ((const float4*)(x + (size_t)gr * DD))[c4];
            if (in_sel == 1) {
                float den = g_den[(size_t)gr * HH + (c4 >> 3)];
                float inv = (den > 0.f) ? (1.f / den) : 0.f;
                val.x *= inv; val.y *= inv; val.z *= inv; val.w *= inv;
            }
        }
        float4 t;
        t.x = __uint_as_float(to_tf32(val.x));
        t.y = __uint_as_float(to_tf32(val.y));
        t.z = __uint_as_float(to_tf32(val.z));
        t.w = __uint_as_float(to_tf32(val.w));
        *(float4*)&xs[r][c4 * 4] = t;
    }
    if (tid < 64) {
        int gr = row0 + tid;
        ts[tid] = ntype[gr < NN ? gr : NN - 1];
    }
    __syncthreads();

    const float* Wmat[3] = {W0, W1, W2};
    float* Omat[3] = {(nmat == 1) ? g_ha : g_k, g_q, g_v};
    bool homog = (ts[0] == ts[63]);

    int warp = tid >> 5, lane = tid & 31;
    int g = lane >> 2, tg = lane & 3;
    int wm = warp & 3, wn = warp >> 2;
    int m0 = wm * 16;

    if (homog) {
        for (int m = 0; m < nmat; ++m) {
            const float* Wt = Wmat[m] + (size_t)ts[0] * DD * DD;
            float acc[8][4];
#pragma unroll
            for (int a = 0; a < 8; a++)
                acc[a][0] = acc[a][1] = acc[a][2] = acc[a][3] = 0.f;

#pragma unroll
            for (int s = 0; s < 16; ++s) {
                int k0 = s * 8;
                uint32_t a0 = __float_as_uint(xs[m0 + g][k0 + tg]);
                uint32_t a1 = __float_as_uint(xs[m0 + g + 8][k0 + tg]);
                uint32_t a2 = __float_as_uint(xs[m0 + g][k0 + tg + 4]);
                uint32_t a3 = __float_as_uint(xs[m0 + g + 8][k0 + tg + 4]);
                const float* pb0 = Wt + (size_t)(k0 + tg) * DD + wn * 64 + g;
                const float* pb1 = Wt + (size_t)(k0 + tg + 4) * DD + wn * 64 + g;
                uint32_t b0[8], b1[8];
#pragma unroll
                for (int nc = 0; nc < 8; ++nc) {
                    b0[nc] = __float_as_uint(__ldg(pb0 + nc * 8));
                    b1[nc] = __float_as_uint(__ldg(pb1 + nc * 8));
                }
#pragma unroll
                for (int nc = 0; nc < 8; ++nc)
                    mma_tf32(acc[nc], a0, a1, a2, a3, b0[nc], b1[nc]);
            }
            float* out = Omat[m];
            int r1 = row0 + m0 + g, r2 = r1 + 8;
#pragma unroll
            for (int nc = 0; nc < 8; ++nc) {
                int col = wn * 64 + nc * 8 + 2 * tg;
                if (r1 < NN)
                    *(float2*)&out[(size_t)r1 * DD + col] = make_float2(acc[nc][0], acc[nc][1]);
                if (r2 < NN)
                    *(float2*)&out[(size_t)r2 * DD + col] = make_float2(acc[nc][2], acc[nc][3]);
            }
        }
    } else {
        for (int m = 0; m < nmat; ++m) {
            int cx = tid & 31, ry = tid >> 5;
            float acc[8][4];
#pragma unroll
            for (int a = 0; a < 8; a++)
                acc[a][0] = acc[a][1] = acc[a][2] = acc[a][3] = 0.f;
            for (int rr = 0; rr < 8; ++rr) {
                int r = ry * 8 + rr;
                const float* Wt = Wmat[m] + (size_t)ts[r] * DD * DD;
                for (int d = 0; d < DD; ++d) {
                    float xv = xs[r][d];
                    float4 w4 = __ldg((const float4*)(Wt + (size_t)d * DD + cx * 4));
                    acc[rr][0] += xv * w4.x; acc[rr][1] += xv * w4.y;
                    acc[rr][2] += xv * w4.z; acc[rr][3] += xv * w4.w;
                }
            }
            float* out = Omat[m];
#pragma unroll
            for (int rr = 0; rr < 8; ++rr) {
                int gr = row0 + ry * 8 + rr;
                if (gr < NN)
                    ((float4*)(out + (size_t)gr * DD))[cx] =
                        make_float4(acc[rr][0], acc[rr][1], acc[rr][2], acc[rr][3]);
            }
        }
    }
}

// ---------------- fused edge kernel: W staged in SMEM per block ----------------
// Warp = 8 edges x 4 heads (lane: hh = lane>>3, j0 = (lane&7)*4).
// Block = 64 consecutive edges -> one relation (etype sorted); Wa then Wm
// staged in static smem (rows 32KB + sW 16KB = exactly 48KB static limit).
__global__ void __launch_bounds__(256) edge_fused_kernel(
    const int* __restrict__ src, const int* __restrict__ dst,
    const int* __restrict__ etype,
    const float* __restrict__ Wa_, const float* __restrict__ Wm_,
    const float* __restrict__ pri)
{
    __shared__ float rows[8][8][128];   // 32768 B
    __shared__ float sW[4][32][32];     // 16384 B   (total = 49152 B = 48KB)

    const unsigned full = 0xffffffffu;
    int tid = threadIdx.x;
    int w = tid >> 5, lane = tid & 31;
    int e0 = (blockIdx.x * 8 + w) * 8;
    int s_ = 0, d_ = 0, t_ = 0;
    if (lane < 8) { s_ = src[e0 + lane]; d_ = dst[e0 + lane]; t_ = etype[e0 + lane]; }
    int hh = lane >> 3, j0 = (lane & 7) << 2;
    int et0 = __shfl_sync(full, t_, 0);
    int et7 = __shfl_sync(full, t_, 7);
    bool whom = (et0 == et7);

    // per-thread block-homogeneity check (etype sorted, L1-broadcast loads)
    int blockEt = __ldg(etype + blockIdx.x * 64);
    int blockHom = (blockEt == __ldg(etype + blockIdx.x * 64 + 63)) ? 1 : 0;

    // ---- stage k rows ----
#pragma unroll
    for (int e = 0; e < 8; ++e) {
        int sE = __shfl_sync(full, s_, e);
        float4 kv = __ldg(((const float4*)(g_k + (size_t)sE * DD)) + lane);
        *(float4*)&rows[w][e][lane * 4] = kv;
    }

    // ---- load Wa into smem (block-homog only) ----
    if (blockHom) {
        for (int idx = tid; idx < 1024; idx += 256) {   // 1024 float4 = 16KB
            int h = idx >> 8, rem = idx & 255;
            ((float4*)sW)[idx] =
                __ldg(((const float4*)(Wa_ + ((size_t)(h * RR + blockEt)) * DHh * DHh)) + rem);
        }
    }
    __syncthreads();

    float ex[8];
    // ================= phase 1: scores =================
    if (blockHom) {
#pragma unroll
        for (int wv = 0; wv < 2; ++wv) {
            float a[4][4];
#pragma unroll
            for (int e = 0; e < 4; ++e) { a[e][0] = a[e][1] = a[e][2] = a[e][3] = 0.f; }
#pragma unroll
            for (int d4 = 0; d4 < 8; ++d4) {
                float kv[4][4];
#pragma unroll
                for (int e = 0; e < 4; ++e)
                    *(float4*)kv[e] = *(const float4*)&rows[w][wv * 4 + e][hh * 32 + d4 * 4];
#pragma unroll
                for (int di = 0; di < 4; ++di) {
                    float4 w4 = *(const float4*)&sW[hh][d4 * 4 + di][j0];
#pragma unroll
                    for (int e = 0; e < 4; ++e) {
                        float k0 = kv[e][di];
                        a[e][0] += k0 * w4.x; a[e][1] += k0 * w4.y;
                        a[e][2] += k0 * w4.z; a[e][3] += k0 * w4.w;
                    }
                }
            }
#pragma unroll
            for (int e = 0; e < 4; ++e) {
                int eg = wv * 4 + e;
                int dE = __shfl_sync(full, d_, eg);
                float4 q4 = __ldg(((const float4*)(g_q + (size_t)dE * DD)) + lane);
                float p = a[e][0] * q4.x + a[e][1] * q4.y + a[e][2] * q4.z + a[e][3] * q4.w;
                p += __shfl_xor_sync(full, p, 4);
                p += __shfl_xor_sync(full, p, 2);
                p += __shfl_xor_sync(full, p, 1);
                float scv = p * __ldg(pri + hh * RR + blockEt) * 0.17677669529663687f;
                float exv = expf(scv);
                ex[eg] = exv;
                if ((lane & 7) == 0)
                    atomicAdd(g_den + (size_t)dE * HH + hh, exv);
            }
        }
    } else if (whom) {   // warp-homog, global W (boundary blocks)
#pragma unroll
        for (int wv = 0; wv < 2; ++wv) {
            float a[4][4];
#pragma unroll
            for (int e = 0; e < 4; ++e) { a[e][0] = a[e][1] = a[e][2] = a[e][3] = 0.f; }
            const float* Wp = Wa_ + ((size_t)(hh * RR + et0)) * DHh * DHh + j0;
#pragma unroll
            for (int d4 = 0; d4 < 8; ++d4) {
                float kv[4][4];
#pragma unroll
                for (int e = 0; e < 4; ++e)
                    *(float4*)kv[e] = *(const float4*)&rows[w][wv * 4 + e][hh * 32 + d4 * 4];
#pragma unroll
                for (int di = 0; di < 4; ++di) {
                    float4 w4 = __ldg((const float4*)(Wp + (d4 * 4 + di) * DHh));
#pragma unroll
                    for (int e = 0; e < 4; ++e) {
                        float k0 = kv[e][di];
                        a[e][0] += k0 * w4.x; a[e][1] += k0 * w4.y;
                        a[e][2] += k0 * w4.z; a[e][3] += k0 * w4.w;
                    }
                }
            }
#pragma unroll
            for (int e = 0; e < 4; ++e) {
                int eg = wv * 4 + e;
                int dE = __shfl_sync(full, d_, eg);
                float4 q4 = __ldg(((const float4*)(g_q + (size_t)dE * DD)) + lane);
                float p = a[e][0] * q4.x + a[e][1] * q4.y + a[e][2] * q4.z + a[e][3] * q4.w;
                p += __shfl_xor_sync(full, p, 4);
                p += __shfl_xor_sync(full, p, 2);
                p += __shfl_xor_sync(full, p, 1);
                float scv = p * __ldg(pri + hh * RR + et0) * 0.17677669529663687f;
                float exv = expf(scv);
                ex[eg] = exv;
                if ((lane & 7) == 0)
                    atomicAdd(g_den + (size_t)dE * HH + hh, exv);
            }
        }
    } else {   // mixed etype within warp (very rare)
#pragma unroll 1
        for (int e = 0; e < 8; ++e) {
            int et = __shfl_sync(full, t_, e);
            int dE = __shfl_sync(full, d_, e);
            const float* Wp = Wa_ + ((size_t)(hh * RR + et)) * DHh * DHh + j0;
            float a0 = 0.f, a1 = 0.f, a2 = 0.f, a3 = 0.f;
            for (int d = 0; d < DHh; ++d) {
                float k0 = rows[w][e][hh * 32 + d];
                float4 w4 = __ldg((const float4*)(Wp + d * DHh));
                a0 += k0 * w4.x; a1 += k0 * w4.y; a2 += k0 * w4.z; a3 += k0 * w4.w;
            }
            float4 q4 = __ldg(((const float4*)(g_q + (size_t)dE * DD)) + lane);
            float p = a0 * q4.x + a1 * q4.y + a2 * q4.z + a3 * q4.w;
            p += __shfl_xor_sync(full, p, 4);
            p += __shfl_xor_sync(full, p, 2);
            p += __shfl_xor_sync(full, p, 1);
            float scv = p * __ldg(pri + hh * RR + et) * 0.17677669529663687f;
            float exv = expf(scv);
            ex[e] = exv;
            if ((lane & 7) == 0)
                atomicAdd(g_den + (size_t)dE * HH + hh, exv);
        }
    }
    __syncthreads();

    // ---- load Wm into smem; stage v rows ----
    if (blockHom) {
        for (int idx = tid; idx < 1024; idx += 256) {
            int h = idx >> 8, rem = idx & 255;
            ((float4*)sW)[idx] =
                __ldg(((const float4*)(Wm_ + ((size_t)(h * RR + blockEt)) * DHh * DHh)) + rem);
        }
    }
#pragma unroll
    for (int e = 0; e < 8; ++e) {
        int sE = __shfl_sync(full, s_, e);
        float4 vv = __ldg(((const float4*)(g_v + (size_t)sE * DD)) + lane);
        *(float4*)&rows[w][e][lane * 4] = vv;
    }
    __syncthreads();

    // ================= phase 2: messages + scatter =================
    if (blockHom) {
#pragma unroll
        for (int wv = 0; wv < 2; ++wv) {
            float a[4][4];
#pragma unroll
            for (int e = 0; e < 4; ++e) { a[e][0] = a[e][1] = a[e][2] = a[e][3] = 0.f; }
#pragma unroll
            for (int d4 = 0; d4 < 8; ++d4) {
                float kv[4][4];
#pragma unroll
                for (int e = 0; e < 4; ++e)
                    *(float4*)kv[e] = *(const float4*)&rows[w][wv * 4 + e][hh * 32 + d4 * 4];
#pragma unroll
                for (int di = 0; di < 4; ++di) {
                    float4 w4 = *(const float4*)&sW[hh][d4 * 4 + di][j0];
#pragma unroll
                    for (int e = 0; e < 4; ++e) {
                        float v0 = kv[e][di];
                        a[e][0] += v0 * w4.x; a[e][1] += v0 * w4.y;
                        a[e][2] += v0 * w4.z; a[e][3] += v0 * w4.w;
                    }
                }
            }
#pragma unroll
            for (int e = 0; e < 4; ++e) {
                int eg = wv * 4 + e;
                int dE = __shfl_sync(full, d_, eg);
                float exv = ex[eg];
                float* p = g_agg + (size_t)dE * DD + hh * DHh + j0;
                asm volatile("red.global.add.v4.f32 [%0], {%1,%2,%3,%4};"
                             :: "l"(p), "f"(a[e][0] * exv), "f"(a[e][1] * exv),
                                "f"(a[e][2] * exv), "f"(a[e][3] * exv)
                             : "memory");
            }
        }
    } else if (whom) {
#pragma unroll
        for (int wv = 0; wv < 2; ++wv) {
            float a[4][4];
#pragma unroll
            for (int e = 0; e < 4; ++e) { a[e][0] = a[e][1] = a[e][2] = a[e][3] = 0.f; }
            const float* Wp = Wm_ + ((size_t)(hh * RR + et0)) * DHh * DHh + j0;
#pragma unroll
            for (int d4 = 0; d4 < 8; ++d4) {
                float kv[4][4];
#pragma unroll
                for (int e = 0; e < 4; ++e)
                    *(float4*)kv[e] = *(const float4*)&rows[w][wv * 4 + e][hh * 32 + d4 * 4];
#pragma unroll
                for (int di = 0; di < 4; ++di) {
                    float4 w4 = __ldg((const float4*)(Wp + (d4 * 4 + di) * DHh));
#pragma unroll
                    for (int e = 0; e < 4; ++e) {
                        float v0 = kv[e][di];
                        a[e][0] += v0 * w4.x; a[e][1] += v0 * w4.y;
                        a[e][2] += v0 * w4.z; a[e][3] += v0 * w4.w;
                    }
                }
            }
#pragma unroll
            for (int e = 0; e < 4; ++e) {
                int eg = wv * 4 + e;
                int dE = __shfl_sync(full, d_, eg);
                float exv = ex[eg];
                float* p = g_agg + (size_t)dE * DD + hh * DHh + j0;
                asm volatile("red.global.add.v4.f32 [%0], {%1,%2,%3,%4};"
                             :: "l"(p), "f"(a[e][0] * exv), "f"(a[e][1] * exv),
                                "f"(a[e][2] * exv), "f"(a[e][3] * exv)
                             : "memory");
            }
        }
    } else {
#pragma unroll 1
        for (int e = 0; e < 8; ++e) {
            int et = __shfl_sync(full, t_, e);
            int dE = __shfl_sync(full, d_, e);
            const float* Wp = Wm_ + ((size_t)(hh * RR + et)) * DHh * DHh + j0;
            float a0 = 0.f, a1 = 0.f, a2 = 0.f, a3 = 0.f;
            for (int d = 0; d < DHh; ++d) {
                float v0 = rows[w][e][hh * 32 + d];
                float4 w4 = __ldg((const float4*)(Wp + d * DHh));
                a0 += v0 * w4.x; a1 += v0 * w4.y; a2 += v0 * w4.z; a3 += v0 * w4.w;
            }
            float exv = ex[e];
            float* p = g_agg + (size_t)dE * DD + hh * DHh + j0;
            asm volatile("red.global.add.v4.f32 [%0], {%1,%2,%3,%4};"
                         :: "l"(p), "f"(a0 * exv), "f"(a1 * exv),
                            "f"(a2 * exv), "f"(a3 * exv)
                         : "memory");
        }
    }
}

// ---------------- skip gate + residual + layernorm ----------------
__global__ void fuse_ln_kernel(const float* __restrict__ xext, int in_sel,
                               const int* __restrict__ ntype,
                               const float* __restrict__ skp, const float* __restrict__ gg,
                               const float* __restrict__ bb, int out_sel)
{
    const float* xin = (in_sel == 0) ? xext : (const float*)g_o0;
    float* xout = (out_sel == 0) ? g_o0 : g_o1;
    int node = (blockIdx.x * blockDim.x + threadIdx.x) >> 5;
    int lane = threadIdx.x & 31;
    if (node >= NN) return;
    float4 x4 = ((const float4*)(xin + (size_t)node * DD))[lane];
    float4 a4 = ((const float4*)(g_ha + (size_t)node * DD))[lane];
    float sk = 1.f / (1.f + expf(-__ldg(skp + ntype[node])));
    float c = 2.f - sk;
    float4 z = make_float4(x4.x * c + a4.x * sk, x4.y * c + a4.y * sk,
                           x4.z * c + a4.z * sk, x4.w * c + a4.w * sk);
    float s = z.x + z.y + z.z + z.w;
#pragma unroll
    for (int o = 16; o > 0; o >>= 1) s += __shfl_xor_sync(0xffffffffu, s, o);
    float mu = s * (1.0f / DD);
    float dx = z.x - mu, dy = z.y - mu, dz = z.z - mu, dw = z.w - mu;
    float vs = dx * dx + dy * dy + dz * dz + dw * dw;
#pragma unroll
    for (int o = 16; o > 0; o >>= 1) vs += __shfl_xor_sync(0xffffffffu, vs, o);
    float inv = rsqrtf(vs * (1.0f / DD) + EPSV);
    float4 g4 = ((const float4*)gg)[lane];
    float4 b4 = ((const float4*)bb)[lane];
    ((float4*)(xout + (size_t)node * DD))[lane] =
        make_float4(dx * inv * g4.x + b4.x, dy * inv * g4.y + b4.y,
                    dz * inv * g4.z + b4.z, dw * inv * g4.w + b4.w);
}

// ---------------- layer aggregation + final layernorm ----------------
__global__ void final_kernel(const float* __restrict__ aw, const float* __restrict__ gg,
                             const float* __restrict__ bb, float* __restrict__ out)
{
    int node = (blockIdx.x * blockDim.x + threadIdx.x) >> 5;
    int lane = threadIdx.x & 31;
    if (node >= NN) return;
    float a0 = __ldg(aw), a1 = __ldg(aw + 1);
    float mw = fmaxf(a0, a1);
    float e0 = expf(a0 - mw), e1 = expf(a1 - mw);
    float den = e0 + e1;
    float w0 = e0 / den, w1 = e1 / den;
    float4 x0 = ((const float4*)(g_o0 + (size_t)node * DD))[lane];
    float4 x1 = ((const float4*)(g_o1 + (size_t)node * DD))[lane];
    float4 z = make_float4(w0 * x0.x + w1 * x1.x, w0 * x0.y + w1 * x1.y,
                           w0 * x0.z + w1 * x1.z, w0 * x0.w + w1 * x1.w);
    float s = z.x + z.y + z.z + z.w;
#pragma unroll
    for (int o = 16; o > 0; o >>= 1) s += __shfl_xor_sync(0xffffffffu, s, o);
    float mu = s * (1.0f / DD);
    float dx = z.x - mu, dy = z.y - mu, dz = z.z - mu, dw = z.w - mu;
    float vs = dx * dx + dy * dy + dz * dz + dw * dw;
#pragma unroll
    for (int o = 16; o > 0; o >>= 1) vs += __shfl_xor_sync(0xffffffffu, vs, o);
    float inv = rsqrtf(vs * (1.0f / DD) + EPSV);
    float4 g4 = ((const float4*)gg)[lane];
    float4 b4 = ((const float4*)bb)[lane];
    ((float4*)(out + (size_t)node * DD))[lane] =
        make_float4(dx * inv * g4.x + b4.x, dy * inv * g4.y + b4.y,
                    dz * inv * g4.z + b4.z, dw * inv * g4.w + b4.w);
}

// ---------------- launch ----------------
extern "C" void kernel_launch(void* const* d_in, const int* in_sizes, int n_in,
                              void* d_out, int out_size)
{
    (void)in_sizes; (void)n_in; (void)out_size;
    const float* h    = (const float*)d_in[0];
    const int*   src  = (const int*)d_in[1];
    const int*   dst  = (const int*)d_in[2];
    const int*   ntyp = (const int*)d_in[3];
    const int*   etyp = (const int*)d_in[4];
    const float* Wk   = (const float*)d_in[5];
    const float* Wq   = (const float*)d_in[6];
    const float* Wv   = (const float*)d_in[7];
    const float* Wa   = (const float*)d_in[8];
    const float* Watt = (const float*)d_in[9];
    const float* Wmsg = (const float*)d_in[10];
    const float* pri  = (const float*)d_in[11];
    const float* skip = (const float*)d_in[12];
    const float* lng  = (const float*)d_in[13];
    const float* lnb  = (const float*)d_in[14];
    const float* aggw = (const float*)d_in[15];
    const float* aggg = (const float*)d_in[16];
    const float* aggb = (const float*)d_in[17];

    const size_t WS = (size_t)TT * DD * DD;
    const size_t ES = (size_t)HH * RR * DHh * DHh;
    const int TL_GRID = (NN + 63) / 64;
    const int NODE_GRID = (NN + 7) / 8;
    const int INIT_GRID = (NN * DD / 4 + 255) / 256;

    for (int l = 0; l < LLn; ++l) {
        int in_sel = (l == 0) ? 0 : 2;
        int ln_out = (l == 0) ? 0 : 1;
        init_kernel<<<INIT_GRID, 256>>>();
        typed_linear_kernel<<<TL_GRID, 256>>>(h, in_sel, ntyp,
                                              Wk + l * WS, Wq + l * WS, Wv + l * WS, 3);
        edge_fused_kernel<<<EDGE_GRID, 256>>>(src, dst, etyp,
                                              Watt + l * ES, Wmsg + l * ES,
                                              pri + l * HH * RR);
        typed_linear_kernel<<<TL_GRID, 256>>>(h, 1, ntyp,
                                              Wa + l * WS, Wa + l * WS, Wa + l * WS, 1);
        fuse_ln_kernel<<<NODE_GRID, 256>>>(h, in_sel, ntyp, skip + l * TT,
                                           lng + l * DD, lnb + l * DD, ln_out);
    }
    final_kernel<<<NODE_GRID, 256>>>(aggw, aggg, aggb, (float*)d_out);
}

// round 16
// speedup vs baseline: 1.4085x; 1.4085x over previous
#include <cuda_runtime.h>
#include <cstdint>

#define NN 50000
#define EE 400000
#define DD 128
#define HH 4
#define DHh 32
#define TT 3
#define RR 6
#define LLn 2
#define EPSV 1e-5f

#define EDGE_GRID (EE / 64)

// ---------------- static scratch (no allocations allowed) ----------------
__device__ float g_k[NN * DD];
__device__ float g_q[NN * DD];
__device__ float g_v[NN * DD];
__device__ float g_agg[NN * DD];
__device__ float g_ha[NN * DD];
__device__ float g_o0[NN * DD];
__device__ float g_o1[NN * DD];
__device__ float g_den[NN * HH];

__device__ __forceinline__ uint32_t to_tf32(float v) {
    uint32_t r;
    asm("cvt.rna.tf32.f32 %0, %1;" : "=r"(r) : "f"(v));
    return r;
}

__device__ __forceinline__ void mma_tf32(float* c, uint32_t a0, uint32_t a1,
                                         uint32_t a2, uint32_t a3,
                                         uint32_t b0, uint32_t b1) {
    asm volatile(
        "mma.sync.aligned.m16n8k8.row.col.f32.tf32.tf32.f32 "
        "{%0,%1,%2,%3}, {%4,%5,%6,%7}, {%8,%9}, {%0,%1,%2,%3};"
        : "+f"(c[0]), "+f"(c[1]), "+f"(c[2]), "+f"(c[3])
        : "r"(a0), "r"(a1), "r"(a2), "r"(a3), "r"(b0), "r"(b1));
}

// ---------------- init: zero g_agg + g_den ----------------
__global__ void __launch_bounds__(256) init_kernel() {
    int i = blockIdx.x * blockDim.x + threadIdx.x;
    if (i < NN * DD / 4)
        ((float4*)g_agg)[i] = make_float4(0.f, 0.f, 0.f, 0.f);
    if (i < NN * HH)
        g_den[i] = 0.f;
}

// ---------------- tf32 typed linear: 128-row tile, m32n64 warps ----------------
// nmat=3: {g_k,g_q,g_v} = x @ {W0,W1,W2}[ntype] ; nmat=1: g_ha = (g_agg/den)@W0
// K staged in two 64-col halves (xs fits 48KB static). 8 warps = 4(M:m32)x2(N:n64).
// Per k-step: 8 A-LDS + 16 B-LDG feed 16 mma (B shared across the 2 m16 frags).
#define XH 68   // half-K row stride: bank (4r+c)&31 -> conflict-free frag reads
__global__ void __launch_bounds__(256, 2) typed_linear_kernel(
    const float* __restrict__ xext, int in_sel,   // 0: ext, 1: g_agg(/den), 2: g_o0
    const int* __restrict__ ntype,
    const float* __restrict__ W0, const float* __restrict__ W1,
    const float* __restrict__ W2, int nmat)
{
    const float* x = (in_sel == 0) ? xext : (in_sel == 1 ? (const float*)g_agg
                                                         : (const float*)g_o0);
    __shared__ float xs[128][XH];
    __shared__ int ts[128];
    int tid = threadIdx.x;
    int row0 = blockIdx.x * 128;

    if (tid < 128) {
        int gr = row0 + tid;
        ts[tid] = ntype[gr < NN ? gr : NN - 1];
    }
    __syncthreads();
    bool homog = (ts[0] == ts[127]);

    const float* Wmat[3] = {W0, W1, W2};
    float* Omat[3] = {(nmat == 1) ? g_ha : g_k, g_q, g_v};

    int warp = tid >> 5, lane = tid & 31;
    int g = lane >> 2, tg = lane & 3;
    int wm = warp & 3, wn = warp >> 2;
    int m0 = wm * 32;

    for (int m = 0; m < nmat; ++m) {
        if (homog) {
            const float* Wt = Wmat[m] + (size_t)ts[0] * DD * DD;
            float acc[2][8][4];
#pragma unroll
            for (int f = 0; f < 2; ++f)
#pragma unroll
                for (int a = 0; a < 8; a++)
                    acc[f][a][0] = acc[f][a][1] = acc[f][a][2] = acc[f][a][3] = 0.f;

#pragma unroll
            for (int h = 0; h < 2; ++h) {
                __syncthreads();
                // stage K-half h (tf32-converted): 2048 float4, 8 per thread
                for (int i = tid; i < 128 * 16; i += 256) {
                    int r = i >> 4, c4 = i & 15;
                    int gr = row0 + r;
                    float4 val = make_float4(0.f, 0.f, 0.f, 0.f);
                    if (gr < NN) {
                        val = ((const float4*)(x + (size_t)gr * DD))[h * 16 + c4];
                        if (in_sel == 1) {
                            float den = g_den[(size_t)gr * HH + ((h * 16 + c4) >> 3)];
                            float inv = (den > 0.f) ? (1.f / den) : 0.f;
                            val.x *= inv; val.y *= inv; val.z *= inv; val.w *= inv;
                        }
                    }
                    float4 t;
                    t.x = __uint_as_float(to_tf32(val.x));
                    t.y = __uint_as_float(to_tf32(val.y));
                    t.z = __uint_as_float(to_tf32(val.z));
                    t.w = __uint_as_float(to_tf32(val.w));
                    *(float4*)&xs[r][c4 * 4] = t;
                }
                __syncthreads();
#pragma unroll
                for (int s = 0; s < 8; ++s) {
                    int kl = s * 8;
                    uint32_t a0 = __float_as_uint(xs[m0 + g][kl + tg]);
                    uint32_t a1 = __float_as_uint(xs[m0 + g + 8][kl + tg]);
                    uint32_t a2 = __float_as_uint(xs[m0 + g][kl + tg + 4]);
                    uint32_t a3 = __float_as_uint(xs[m0 + g + 8][kl + tg + 4]);
                    uint32_t a4 = __float_as_uint(xs[m0 + g + 16][kl + tg]);
                    uint32_t a5 = __float_as_uint(xs[m0 + g + 24][kl + tg]);
                    uint32_t a6 = __float_as_uint(xs[m0 + g + 16][kl + tg + 4]);
                    uint32_t a7 = __float_as_uint(xs[m0 + g + 24][kl + tg + 4]);
                    int kg = h * 64 + s * 8;
                    const float* pb0 = Wt + (size_t)(kg + tg) * DD + wn * 64 + g;
                    const float* pb1 = Wt + (size_t)(kg + tg + 4) * DD + wn * 64 + g;
                    uint32_t b0[8], b1[8];
#pragma unroll
                    for (int nc = 0; nc < 8; ++nc) {
                        b0[nc] = __float_as_uint(__ldg(pb0 + nc * 8));
                        b1[nc] = __float_as_uint(__ldg(pb1 + nc * 8));
                    }
#pragma unroll
                    for (int nc = 0; nc < 8; ++nc) {
                        mma_tf32(acc[0][nc], a0, a1, a2, a3, b0[nc], b1[nc]);
                        mma_tf32(acc[1][nc], a4, a5, a6, a7, b0[nc], b1[nc]);
                    }
                }
            }
            float* out = Omat[m];
            int r1 = row0 + m0 + g;       // frag0 rows: r1, r1+8
            int r3 = r1 + 16;             // frag1 rows: r3, r3+8
#pragma unroll
            for (int nc = 0; nc < 8; ++nc) {
                int col = wn * 64 + nc * 8 + 2 * tg;
                if (r1 < NN)
                    *(float2*)&out[(size_t)r1 * DD + col] = make_float2(acc[0][nc][0], acc[0][nc][1]);
                if (r1 + 8 < NN)
                    *(float2*)&out[(size_t)(r1 + 8) * DD + col] = make_float2(acc[0][nc][2], acc[0][nc][3]);
                if (r3 < NN)
                    *(float2*)&out[(size_t)r3 * DD + col] = make_float2(acc[1][nc][0], acc[1][nc][1]);
                if (r3 + 8 < NN)
                    *(float2*)&out[(size_t)(r3 + 8) * DD + col] = make_float2(acc[1][nc][2], acc[1][nc][3]);
            }
        } else {
            // boundary block: scalar fp32 path, 16 rows per warp, halves accumulated
            int cx = lane;
            float acc[16][4];
#pragma unroll
            for (int a = 0; a < 16; a++)
                acc[a][0] = acc[a][1] = acc[a][2] = acc[a][3] = 0.f;
#pragma unroll
            for (int h = 0; h < 2; ++h) {
                __syncthreads();
                for (int i = tid; i < 128 * 16; i += 256) {
                    int r = i >> 4, c4 = i & 15;
                    int gr = row0 + r;
                    float4 val = make_float4(0.f, 0.f, 0.f, 0.f);
                    if (gr < NN) {
                        val = ((const float4*)(x + (size_t)gr * DD))[h * 16 + c4];
                        if (in_sel == 1) {
                            float den = g_den[(size_t)gr * HH + ((h * 16 + c4) >> 3)];
                            float inv = (den > 0.f) ? (1.f / den) : 0.f;
                            val.x *= inv; val.y *= inv; val.z *= inv; val.w *= inv;
                        }
                    }
                    *(float4*)&xs[r][c4 * 4] = val;   // fp32, no conversion
                }
                __syncthreads();
                for (int rr = 0; rr < 16; ++rr) {
                    int r = warp * 16 + rr;
                    const float* Wt = Wmat[m] + (size_t)ts[r] * DD * DD;
                    for (int d = 0; d < 64; ++d) {
                        float xv = xs[r][d];
                        float4 w4 = __ldg((const float4*)(Wt + (size_t)(h * 64 + d) * DD + cx * 4));
                        acc[rr][0] += xv * w4.x; acc[rr][1] += xv * w4.y;
                        acc[rr][2] += xv * w4.z; acc[rr][3] += xv * w4.w;
                    }
                }
            }
            float* out = Omat[m];
#pragma unroll
            for (int rr = 0; rr < 16; ++rr) {
                int gr = row0 + warp * 16 + rr;
                if (gr < NN)
                    ((float4*)(out + (size_t)gr * DD))[cx] =
                        make_float4(acc[rr][0], acc[rr][1], acc[rr][2], acc[rr][3]);
            }
        }
        if (m + 1 < nmat) __syncthreads();
    }
}

// ---------------- fused edge kernel (exact R10 version) ----------------
__global__ void __launch_bounds__(256) edge_fused_kernel(
    const int* __restrict__ src, const int* __restrict__ dst,
    const int* __restrict__ etype,
    const float* __restrict__ Wa_, const float* __restrict__ Wm_,
    const float* __restrict__ pri)
{
    __shared__ float rows[8][8][144];
    const unsigned full = 0xffffffffu;
    int w = threadIdx.x >> 5, lane = threadIdx.x & 31;
    int e0 = (blockIdx.x * 8 + w) * 8;
    int s_ = 0, d_ = 0, t_ = 0;
    if (lane < 8) { s_ = src[e0 + lane]; d_ = dst[e0 + lane]; t_ = etype[e0 + lane]; }
    int hh = lane >> 3, j0 = (lane & 7) << 2;
    int et0 = __shfl_sync(full, t_, 0);
    int et7 = __shfl_sync(full, t_, 7);
    bool homog = (et0 == et7);
    float ex[8];

#pragma unroll
    for (int e = 0; e < 8; ++e) {
        int sE = __shfl_sync(full, s_, e);
        float4 kv = __ldg(((const float4*)(g_k + (size_t)sE * DD)) + lane);
        *(float4*)&rows[w][e][hh * 36 + j0] = kv;
    }
    __syncwarp();

#pragma unroll
    for (int wv = 0; wv < 2; ++wv) {
        float a[4][4];
#pragma unroll
        for (int e = 0; e < 4; ++e) { a[e][0] = a[e][1] = a[e][2] = a[e][3] = 0.f; }

        if (homog) {
            const float* Wp = Wa_ + ((size_t)(hh * RR + et0)) * DHh * DHh + j0;
#pragma unroll
            for (int d4 = 0; d4 < 8; ++d4) {
                float kv[4][4];
#pragma unroll
                for (int e = 0; e < 4; ++e)
                    *(float4*)kv[e] = *(const float4*)&rows[w][wv * 4 + e][hh * 36 + d4 * 4];
#pragma unroll
                for (int di = 0; di < 4; ++di) {
                    float4 w4 = __ldg((const float4*)(Wp + (d4 * 4 + di) * DHh));
#pragma unroll
                    for (int e = 0; e < 4; ++e) {
                        float k0 = kv[e][di];
                        a[e][0] += k0 * w4.x; a[e][1] += k0 * w4.y;
                        a[e][2] += k0 * w4.z; a[e][3] += k0 * w4.w;
                    }
                }
            }
        } else {
#pragma unroll 1
            for (int e = 0; e < 4; ++e) {
                int et = __shfl_sync(full, t_, wv * 4 + e);
                const float* Wp = Wa_ + ((size_t)(hh * RR + et)) * DHh * DHh + j0;
                for (int d = 0; d < DHh; ++d) {
                    float k0 = rows[w][wv * 4 + e][hh * 36 + d];
                    float4 w4 = __ldg((const float4*)(Wp + d * DHh));
                    a[e][0] += k0 * w4.x; a[e][1] += k0 * w4.y;
                    a[e][2] += k0 * w4.z; a[e][3] += k0 * w4.w;
                }
            }
        }

#pragma unroll
        for (int e = 0; e < 4; ++e) {
            int eg = wv * 4 + e;
            int dE = __shfl_sync(full, d_, eg);
            int et = __shfl_sync(full, t_, eg);
            float4 q4 = __ldg(((const float4*)(g_q + (size_t)dE * DD)) + lane);
            float p = a[e][0] * q4.x + a[e][1] * q4.y + a[e][2] * q4.z + a[e][3] * q4.w;
            p += __shfl_xor_sync(full, p, 4);
            p += __shfl_xor_sync(full, p, 2);
            p += __shfl_xor_sync(full, p, 1);
            float scv = p * __ldg(pri + hh * RR + et) * 0.17677669529663687f;
            float exv = expf(scv);
            ex[eg] = exv;
            if ((lane & 7) == 0)
                atomicAdd(g_den + (size_t)dE * HH + hh, exv);
        }
    }
    __syncwarp();

#pragma unroll
    for (int e = 0; e < 8; ++e) {
        int sE = __shfl_sync(full, s_, e);
        float4 vv = __ldg(((const float4*)(g_v + (size_t)sE * DD)) + lane);
        *(float4*)&rows[w][e][hh * 36 + j0] = vv;
    }
    __syncwarp();

#pragma unroll
    for (int wv = 0; wv < 2; ++wv) {
        float a[4][4];
#pragma unroll
        for (int e = 0; e < 4; ++e) { a[e][0] = a[e][1] = a[e][2] = a[e][3] = 0.f; }

        if (homog) {
            const float* Wp = Wm_ + ((size_t)(hh * RR + et0)) * DHh * DHh + j0;
#pragma unroll
            for (int d4 = 0; d4 < 8; ++d4) {
                float kv[4][4];
#pragma unroll
                for (int e = 0; e < 4; ++e)
                    *(float4*)kv[e] = *(const float4*)&rows[w][wv * 4 + e][hh * 36 + d4 * 4];
#pragma unroll
                for (int di = 0; di < 4; ++di) {
                    float4 w4 = __ldg((const float4*)(Wp + (d4 * 4 + di) * DHh));
#pragma unroll
                    for (int e = 0; e < 4; ++e) {
                        float v0 = kv[e][di];
                        a[e][0] += v0 * w4.x; a[e][1] += v0 * w4.y;
                        a[e][2] += v0 * w4.z; a[e][3] += v0 * w4.w;
                    }
                }
            }
        } else {
#pragma unroll 1
            for (int e = 0; e < 4; ++e) {
                int et = __shfl_sync(full, t_, wv * 4 + e);
                const float* Wp = Wm_ + ((size_t)(hh * RR + et)) * DHh * DHh + j0;
                for (int d = 0; d < DHh; ++d) {
                    float v0 = rows[w][wv * 4 + e][hh * 36 + d];
                    float4 w4 = __ldg((const float4*)(Wp + d * DHh));
                    a[e][0] += v0 * w4.x; a[e][1] += v0 * w4.y;
                    a[e][2] += v0 * w4.z; a[e][3] += v0 * w4.w;
                }
            }
        }

#pragma unroll
        for (int e = 0; e < 4; ++e) {
            int eg = wv * 4 + e;
            int dE = __shfl_sync(full, d_, eg);
            float exv = ex[eg];
            float* p = g_agg + (size_t)dE * DD + hh * DHh + j0;
            asm volatile("red.global.add.v4.f32 [%0], {%1,%2,%3,%4};"
                         :: "l"(p), "f"(a[e][0] * exv), "f"(a[e][1] * exv),
                            "f"(a[e][2] * exv), "f"(a[e][3] * exv)
                         : "memory");
        }
    }
}

// ---------------- skip gate + residual + layernorm ----------------
__global__ void fuse_ln_kernel(const float* __restrict__ xext, int in_sel,
                               const int* __restrict__ ntype,
                               const float* __restrict__ skp, const float* __restrict__ gg,
                               const float* __restrict__ bb, int out_sel)
{
    const float* xin = (in_sel == 0) ? xext : (const float*)g_o0;
    float* xout = (out_sel == 0) ? g_o0 : g_o1;
    int node = (blockIdx.x * blockDim.x + threadIdx.x) >> 5;
    int lane = threadIdx.x & 31;
    if (node >= NN) return;
    float4 x4 = ((const float4*)(xin + (size_t)node * DD))[lane];
    float4 a4 = ((const float4*)(g_ha + (size_t)node * DD))[lane];
    float sk = 1.f / (1.f + expf(-__ldg(skp + ntype[node])));
    float c = 2.f - sk;
    float4 z = make_float4(x4.x * c + a4.x * sk, x4.y * c + a4.y * sk,
                           x4.z * c + a4.z * sk, x4.w * c + a4.w * sk);
    float s = z.x + z.y + z.z + z.w;
#pragma unroll
    for (int o = 16; o > 0; o >>= 1) s += __shfl_xor_sync(0xffffffffu, s, o);
    float mu = s * (1.0f / DD);
    float dx = z.x - mu, dy = z.y - mu, dz = z.z - mu, dw = z.w - mu;
    float vs = dx * dx + dy * dy + dz * dz + dw * dw;
#pragma unroll
    for (int o = 16; o > 0; o >>= 1) vs += __shfl_xor_sync(0xffffffffu, vs, o);
    float inv = rsqrtf(vs * (1.0f / DD) + EPSV);
    float4 g4 = ((const float4*)gg)[lane];
    float4 b4 = ((const float4*)bb)[lane];
    ((float4*)(xout + (size_t)node * DD))[lane] =
        make_float4(dx * inv * g4.x + b4.x, dy * inv * g4.y + b4.y,
                    dz * inv * g4.z + b4.z, dw * inv * g4.w + b4.w);
}

// ---------------- layer aggregation + final layernorm ----------------
__global__ void final_kernel(const float* __restrict__ aw, const float* __restrict__ gg,
                             const float* __restrict__ bb, float* __restrict__ out)
{
    int node = (blockIdx.x * blockDim.x + threadIdx.x) >> 5;
    int lane = threadIdx.x & 31;
    if (node >= NN) return;
    float a0 = __ldg(aw), a1 = __ldg(aw + 1);
    float mw = fmaxf(a0, a1);
    float e0 = expf(a0 - mw), e1 = expf(a1 - mw);
    float den = e0 + e1;
    float w0 = e0 / den, w1 = e1 / den;
    float4 x0 = ((const float4*)(g_o0 + (size_t)node * DD))[lane];
    float4 x1 = ((const float4*)(g_o1 + (size_t)node * DD))[lane];
    float4 z = make_float4(w0 * x0.x + w1 * x1.x, w0 * x0.y + w1 * x1.y,
                           w0 * x0.z + w1 * x1.z, w0 * x0.w + w1 * x1.w);
    float s = z.x + z.y + z.z + z.w;
#pragma unroll
    for (int o = 16; o > 0; o >>= 1) s += __shfl_xor_sync(0xffffffffu, s, o);
    float mu = s * (1.0f / DD);
    float dx = z.x - mu, dy = z.y - mu, dz = z.z - mu, dw = z.w - mu;
    float vs = dx * dx + dy * dy + dz * dz + dw * dw;
#pragma unroll
    for (int o = 16; o > 0; o >>= 1) vs += __shfl_xor_sync(0xffffffffu, vs, o);
    float inv = rsqrtf(vs * (1.0f / DD) + EPSV);
    float4 g4 = ((const float4*)gg)[lane];
    float4 b4 = ((const float4*)bb)[lane];
    ((float4*)(out + (size_t)node * DD))[lane] =
        make_float4(dx * inv * g4.x + b4.x, dy * inv * g4.y + b4.y,
                    dz * inv * g4.z + b4.z, dw * inv * g4.w + b4.w);
}

// ---------------- launch ----------------
extern "C" void kernel_launch(void* const* d_in, const int* in_sizes, int n_in,
                              void* d_out, int out_size)
{
    (void)in_sizes; (void)n_in; (void)out_size;
    const float* h    = (const float*)d_in[0];
    const int*   src  = (const int*)d_in[1];
    const int*   dst  = (const int*)d_in[2];
    const int*   ntyp = (const int*)d_in[3];
    const int*   etyp = (const int*)d_in[4];
    const float* Wk   = (const float*)d_in[5];
    const float* Wq   = (const float*)d_in[6];
    const float* Wv   = (const float*)d_in[7];
    const float* Wa   = (const float*)d_in[8];
    const float* Watt = (const float*)d_in[9];
    const float* Wmsg = (const float*)d_in[10];
    const float* pri  = (const float*)d_in[11];
    const float* skip = (const float*)d_in[12];
    const float* lng  = (const float*)d_in[13];
    const float* lnb  = (const float*)d_in[14];
    const float* aggw = (const float*)d_in[15];
    const float* aggg = (const float*)d_in[16];
    const float* aggb = (const float*)d_in[17];

    const size_t WS = (size_t)TT * DD * DD;
    const size_t ES = (size_t)HH * RR * DHh * DHh;
    const int TL_GRID = (NN + 127) / 128;
    const int NODE_GRID = (NN + 7) / 8;
    const int INIT_GRID = (NN * DD / 4 + 255) / 256;

    for (int l = 0; l < LLn; ++l) {
        int in_sel = (l == 0) ? 0 : 2;
        int ln_out = (l == 0) ? 0 : 1;
        init_kernel<<<INIT_GRID, 256>>>();
        typed_linear_kernel<<<TL_GRID, 256>>>(h, in_sel, ntyp,
                                              Wk + l * WS, Wq + l * WS, Wv + l * WS, 3);
        edge_fused_kernel<<<EDGE_GRID, 256>>>(src, dst, etyp,
                                              Watt + l * ES, Wmsg + l * ES,
                                              pri + l * HH * RR);
        typed_linear_kernel<<<TL_GRID, 256>>>(h, 1, ntyp,
                                              Wa + l * WS, Wa + l * WS, Wa + l * WS, 1);
        fuse_ln_kernel<<<NODE_GRID, 256>>>(h, in_sel, ntyp, skip + l * TT,
                                           lng + l * DD, lnb + l * DD, ln_out);
    }
    final_kernel<<<NODE_GRID, 256>>>(aggw, aggg, aggb, (float*)d_out);
}

// round 17
// speedup vs baseline: 1.6001x; 1.1361x over previous
#include <cuda_runtime.h>
#include <cstdint>

#define NN 50000
#define EE 400000
#define DD 128
#define HH 4
#define DHh 32
#define TT 3
#define RR 6
#define LLn 2
#define EPSV 1e-5f

#define EDGE_GRID (EE / 64)

// ---------------- static scratch (no allocations allowed) ----------------
__device__ float g_k[NN * DD];
__device__ float g_q[NN * DD];
__device__ float g_v[NN * DD];
__device__ float g_agg[NN * DD];
__device__ float g_ha[NN * DD];
__device__ float g_o0[NN * DD];
__device__ float g_o1[NN * DD];
__device__ float g_den[NN * HH];

__device__ __forceinline__ uint32_t to_tf32(float v) {
    uint32_t r;
    asm("cvt.rna.tf32.f32 %0, %1;" : "=r"(r) : "f"(v));
    return r;
}

__device__ __forceinline__ void mma_tf32(float* c, uint32_t a0, uint32_t a1,
                                         uint32_t a2, uint32_t a3,
                                         uint32_t b0, uint32_t b1) {
    asm volatile(
        "mma.sync.aligned.m16n8k8.row.col.f32.tf32.tf32.f32 "
        "{%0,%1,%2,%3}, {%4,%5,%6,%7}, {%8,%9}, {%0,%1,%2,%3};"
        : "+f"(c[0]), "+f"(c[1]), "+f"(c[2]), "+f"(c[3])
        : "r"(a0), "r"(a1), "r"(a2), "r"(a3), "r"(b0), "r"(b1));
}

// ---------------- init: zero g_agg + g_den ----------------
__global__ void __launch_bounds__(256) init_kernel() {
    int i = blockIdx.x * blockDim.x + threadIdx.x;
    if (i < NN * DD / 4)
        ((float4*)g_agg)[i] = make_float4(0.f, 0.f, 0.f, 0.f);
    if (i < NN * HH)
        g_den[i] = 0.f;
}

// ---------------- tf32 typed linear: smem-B with XOR swizzle ----------------
// Block 64 rows, 8 warps = 4(M:m16) x 2(N:n64).
// x staged per 64-col half (xs[64][68], conflict-free A-frags: 4g+tg bijective).
// W staged per 32-row quarter into ws[32][128] with row-XOR swizzle
//   col' = col ^ ((row&3)*8)  -> B-frag LDS conflict-free (verified 32 banks).
// W gmem traffic: coalesced float4, once per block per matrix.
template<int NMAT>
__global__ void __launch_bounds__(256, 2) typed_linear_kernel(
    const float* __restrict__ xext, int in_sel,   // 0: ext, 1: g_agg(/den), 2: g_o0
    const int* __restrict__ ntype,
    const float* __restrict__ W0, const float* __restrict__ W1,
    const float* __restrict__ W2)
{
    const float* x = (in_sel == 0) ? xext : (in_sel == 1 ? (const float*)g_agg
                                                         : (const float*)g_o0);
    __shared__ float xs[64][68];
    __shared__ float ws[32][128];
    __shared__ int ts[64];
    int tid = threadIdx.x;
    int row0 = blockIdx.x * 64;

    if (tid < 64) {
        int gr = row0 + tid;
        ts[tid] = ntype[gr < NN ? gr : NN - 1];
    }
    __syncthreads();
    bool homog = (ts[0] == ts[63]);

    const float* Wmat[3] = {W0, W1, W2};
    float* Omat[3] = {(NMAT == 1) ? g_ha : g_k, g_q, g_v};

    int warp = tid >> 5, lane = tid & 31;
    int g = lane >> 2, tg = lane & 3;
    int wm = warp & 3, wn = warp >> 2;
    int m0 = wm * 16;

    if (homog) {
        for (int m = 0; m < NMAT; ++m) {
            const float* Wt = Wmat[m] + (size_t)ts[0] * DD * DD;
            float acc[8][4];
#pragma unroll
            for (int a = 0; a < 8; a++)
                acc[a][0] = acc[a][1] = acc[a][2] = acc[a][3] = 0.f;

#pragma unroll
            for (int h = 0; h < 2; ++h) {
                __syncthreads();   // xs, ws free from previous use
                // stage x half h (tf32): 64 rows x 16 float4
                for (int i = tid; i < 64 * 16; i += 256) {
                    int r = i >> 4, c4 = i & 15;
                    int gr = row0 + r;
                    float4 val = make_float4(0.f, 0.f, 0.f, 0.f);
                    if (gr < NN) {
                        val = ((const float4*)(x + (size_t)gr * DD))[h * 16 + c4];
                        if (in_sel == 1) {
                            float den = g_den[(size_t)gr * HH + ((h * 16 + c4) >> 3)];
                            float inv = (den > 0.f) ? (1.f / den) : 0.f;
                            val.x *= inv; val.y *= inv; val.z *= inv; val.w *= inv;
                        }
                    }
                    float4 t;
                    t.x = __uint_as_float(to_tf32(val.x));
                    t.y = __uint_as_float(to_tf32(val.y));
                    t.z = __uint_as_float(to_tf32(val.z));
                    t.w = __uint_as_float(to_tf32(val.w));
                    *(float4*)&xs[r][c4 * 4] = t;
                }
#pragma unroll
                for (int qq = 0; qq < 2; ++qq) {
                    if (qq > 0) __syncthreads();   // ws free after previous quarter
                    // stage W quarter: rows h*64+qq*32 .. +32, xor-swizzled
                    for (int i = tid; i < 32 * 32; i += 256) {
                        int kr = i >> 5, c4 = i & 31;
                        float4 v = ((const float4*)(Wt + (size_t)(h * 64 + qq * 32 + kr) * DD))[c4];
                        int col = (c4 * 4) ^ ((kr & 3) * 8);
                        *(float4*)&ws[kr][col] = v;
                    }
                    __syncthreads();   // xs + ws ready
                    int kq = qq * 32;
#pragma unroll
                    for (int s = 0; s < 4; ++s) {
                        int kl = kq + s * 8;        // xs col base
                        int kw = s * 8;             // ws row base
                        uint32_t a0 = __float_as_uint(xs[m0 + g][kl + tg]);
                        uint32_t a1 = __float_as_uint(xs[m0 + g + 8][kl + tg]);
                        uint32_t a2 = __float_as_uint(xs[m0 + g][kl + tg + 4]);
                        uint32_t a3 = __float_as_uint(xs[m0 + g + 8][kl + tg + 4]);
                        uint32_t b0[8], b1[8];
#pragma unroll
                        for (int nc = 0; nc < 8; ++nc) {
                            int colp = (wn * 64 + nc * 8 + g) ^ (tg * 8);
                            b0[nc] = __float_as_uint(ws[kw + tg][colp]);
                            b1[nc] = __float_as_uint(ws[kw + tg + 4][colp]);
                        }
#pragma unroll
                        for (int nc = 0; nc < 8; ++nc)
                            mma_tf32(acc[nc], a0, a1, a2, a3, b0[nc], b1[nc]);
                    }
                }
            }
            float* out = Omat[m];
            int r1 = row0 + m0 + g, r2 = r1 + 8;
#pragma unroll
            for (int nc = 0; nc < 8; ++nc) {
                int col = wn * 64 + nc * 8 + 2 * tg;
                if (r1 < NN)
                    *(float2*)&out[(size_t)r1 * DD + col] = make_float2(acc[nc][0], acc[nc][1]);
                if (r2 < NN)
                    *(float2*)&out[(size_t)r2 * DD + col] = make_float2(acc[nc][2], acc[nc][3]);
            }
        }
    } else {
        // boundary block: scalar fp32 path (rare; <=2 blocks per type boundary)
        for (int m = 0; m < NMAT; ++m) {
            int cx = lane, ry = warp;
            float acc[8][4];
#pragma unroll
            for (int a = 0; a < 8; a++)
                acc[a][0] = acc[a][1] = acc[a][2] = acc[a][3] = 0.f;
#pragma unroll
            for (int h = 0; h < 2; ++h) {
                __syncthreads();
                for (int i = tid; i < 64 * 16; i += 256) {
                    int r = i >> 4, c4 = i & 15;
                    int gr = row0 + r;
                    float4 val = make_float4(0.f, 0.f, 0.f, 0.f);
                    if (gr < NN) {
                        val = ((const float4*)(x + (size_t)gr * DD))[h * 16 + c4];
                        if (in_sel == 1) {
                            float den = g_den[(size_t)gr * HH + ((h * 16 + c4) >> 3)];
                            float inv = (den > 0.f) ? (1.f / den) : 0.f;
                            val.x *= inv; val.y *= inv; val.z *= inv; val.w *= inv;
                        }
                    }
                    *(float4*)&xs[r][c4 * 4] = val;
                }
                __syncthreads();
                for (int rr = 0; rr < 8; ++rr) {
                    int r = ry * 8 + rr;
                    const float* Wt = Wmat[m] + (size_t)ts[r] * DD * DD;
                    for (int d = 0; d < 64; ++d) {
                        float xv = xs[r][d];
                        float4 w4 = __ldg((const float4*)(Wt + (size_t)(h * 64 + d) * DD + cx * 4));
                        acc[rr][0] += xv * w4.x; acc[rr][1] += xv * w4.y;
                        acc[rr][2] += xv * w4.z; acc[rr][3] += xv * w4.w;
                    }
                }
            }
            float* out = Omat[m];
#pragma unroll
            for (int rr = 0; rr < 8; ++rr) {
                int gr = row0 + ry * 8 + rr;
                if (gr < NN)
                    ((float4*)(out + (size_t)gr * DD))[cx] =
                        make_float4(acc[rr][0], acc[rr][1], acc[rr][2], acc[rr][3]);
            }
        }
    }
}

// ---------------- fused edge kernel (exact R10 version) ----------------
__global__ void __launch_bounds__(256) edge_fused_kernel(
    const int* __restrict__ src, const int* __restrict__ dst,
    const int* __restrict__ etype,
    const float* __restrict__ Wa_, const float* __restrict__ Wm_,
    const float* __restrict__ pri)
{
    __shared__ float rows[8][8][144];
    const unsigned full = 0xffffffffu;
    int w = threadIdx.x >> 5, lane = threadIdx.x & 31;
    int e0 = (blockIdx.x * 8 + w) * 8;
    int s_ = 0, d_ = 0, t_ = 0;
    if (lane < 8) { s_ = src[e0 + lane]; d_ = dst[e0 + lane]; t_ = etype[e0 + lane]; }
    int hh = lane >> 3, j0 = (lane & 7) << 2;
    int et0 = __shfl_sync(full, t_, 0);
    int et7 = __shfl_sync(full, t_, 7);
    bool homog = (et0 == et7);
    float ex[8];

#pragma unroll
    for (int e = 0; e < 8; ++e) {
        int sE = __shfl_sync(full, s_, e);
        float4 kv = __ldg(((const float4*)(g_k + (size_t)sE * DD)) + lane);
        *(float4*)&rows[w][e][hh * 36 + j0] = kv;
    }
    __syncwarp();

#pragma unroll
    for (int wv = 0; wv < 2; ++wv) {
        float a[4][4];
#pragma unroll
        for (int e = 0; e < 4; ++e) { a[e][0] = a[e][1] = a[e][2] = a[e][3] = 0.f; }

        if (homog) {
            const float* Wp = Wa_ + ((size_t)(hh * RR + et0)) * DHh * DHh + j0;
#pragma unroll
            for (int d4 = 0; d4 < 8; ++d4) {
                float kv[4][4];
#pragma unroll
                for (int e = 0; e < 4; ++e)
                    *(float4*)kv[e] = *(const float4*)&rows[w][wv * 4 + e][hh * 36 + d4 * 4];
#pragma unroll
                for (int di = 0; di < 4; ++di) {
                    float4 w4 = __ldg((const float4*)(Wp + (d4 * 4 + di) * DHh));
#pragma unroll
                    for (int e = 0; e < 4; ++e) {
                        float k0 = kv[e][di];
                        a[e][0] += k0 * w4.x; a[e][1] += k0 * w4.y;
                        a[e][2] += k0 * w4.z; a[e][3] += k0 * w4.w;
                    }
                }
            }
        } else {
#pragma unroll 1
            for (int e = 0; e < 4; ++e) {
                int et = __shfl_sync(full, t_, wv * 4 + e);
                const float* Wp = Wa_ + ((size_t)(hh * RR + et)) * DHh * DHh + j0;
                for (int d = 0; d < DHh; ++d) {
                    float k0 = rows[w][wv * 4 + e][hh * 36 + d];
                    float4 w4 = __ldg((const float4*)(Wp + d * DHh));
                    a[e][0] += k0 * w4.x; a[e][1] += k0 * w4.y;
                    a[e][2] += k0 * w4.z; a[e][3] += k0 * w4.w;
                }
            }
        }

#pragma unroll
        for (int e = 0; e < 4; ++e) {
            int eg = wv * 4 + e;
            int dE = __shfl_sync(full, d_, eg);
            int et = __shfl_sync(full, t_, eg);
            float4 q4 = __ldg(((const float4*)(g_q + (size_t)dE * DD)) + lane);
            float p = a[e][0] * q4.x + a[e][1] * q4.y + a[e][2] * q4.z + a[e][3] * q4.w;
            p += __shfl_xor_sync(full, p, 4);
            p += __shfl_xor_sync(full, p, 2);
            p += __shfl_xor_sync(full, p, 1);
            float scv = p * __ldg(pri + hh * RR + et) * 0.17677669529663687f;
            float exv = expf(scv);
            ex[eg] = exv;
            if ((lane & 7) == 0)
                atomicAdd(g_den + (size_t)dE * HH + hh, exv);
        }
    }
    __syncwarp();

#pragma unroll
    for (int e = 0; e < 8; ++e) {
        int sE = __shfl_sync(full, s_, e);
        float4 vv = __ldg(((const float4*)(g_v + (size_t)sE * DD)) + lane);
        *(float4*)&rows[w][e][hh * 36 + j0] = vv;
    }
    __syncwarp();

#pragma unroll
    for (int wv = 0; wv < 2; ++wv) {
        float a[4][4];
#pragma unroll
        for (int e = 0; e < 4; ++e) { a[e][0] = a[e][1] = a[e][2] = a[e][3] = 0.f; }

        if (homog) {
            const float* Wp = Wm_ + ((size_t)(hh * RR + et0)) * DHh * DHh + j0;
#pragma unroll
            for (int d4 = 0; d4 < 8; ++d4) {
                float kv[4][4];
#pragma unroll
                for (int e = 0; e < 4; ++e)
                    *(float4*)kv[e] = *(const float4*)&rows[w][wv * 4 + e][hh * 36 + d4 * 4];
#pragma unroll
                for (int di = 0; di < 4; ++di) {
                    float4 w4 = __ldg((const float4*)(Wp + (d4 * 4 + di) * DHh));
#pragma unroll
                    for (int e = 0; e < 4; ++e) {
                        float v0 = kv[e][di];
                        a[e][0] += v0 * w4.x; a[e][1] += v0 * w4.y;
                        a[e][2] += v0 * w4.z; a[e][3] += v0 * w4.w;
                    }
                }
            }
        } else {
#pragma unroll 1
            for (int e = 0; e < 4; ++e) {
                int et = __shfl_sync(full, t_, wv * 4 + e);
                const float* Wp = Wm_ + ((size_t)(hh * RR + et)) * DHh * DHh + j0;
                for (int d = 0; d < DHh; ++d) {
                    float v0 = rows[w][wv * 4 + e][hh * 36 + d];
                    float4 w4 = __ldg((const float4*)(Wp + d * DHh));
                    a[e][0] += v0 * w4.x; a[e][1] += v0 * w4.y;
                    a[e][2] += v0 * w4.z; a[e][3] += v0 * w4.w;
                }
            }
        }

#pragma unroll
        for (int e = 0; e < 4; ++e) {
            int eg = wv * 4 + e;
            int dE = __shfl_sync(full, d_, eg);
            float exv = ex[eg];
            float* p = g_agg + (size_t)dE * DD + hh * DHh + j0;
            asm volatile("red.global.add.v4.f32 [%0], {%1,%2,%3,%4};"
                         :: "l"(p), "f"(a[e][0] * exv), "f"(a[e][1] * exv),
                            "f"(a[e][2] * exv), "f"(a[e][3] * exv)
                         : "memory");
        }
    }
}

// ---------------- skip gate + residual + layernorm ----------------
__global__ void fuse_ln_kernel(const float* __restrict__ xext, int in_sel,
                               const int* __restrict__ ntype,
                               const float* __restrict__ skp, const float* __restrict__ gg,
                               const float* __restrict__ bb, int out_sel)
{
    const float* xin = (in_sel == 0) ? xext : (const float*)g_o0;
    float* xout = (out_sel == 0) ? g_o0 : g_o1;
    int node = (blockIdx.x * blockDim.x + threadIdx.x) >> 5;
    int lane = threadIdx.x & 31;
    if (node >= NN) return;
    float4 x4 = ((const float4*)(xin + (size_t)node * DD))[lane];
    float4 a4 = ((const float4*)(g_ha + (size_t)node * DD))[lane];
    float sk = 1.f / (1.f + expf(-__ldg(skp + ntype[node])));
    float c = 2.f - sk;
    float4 z = make_float4(x4.x * c + a4.x * sk, x4.y * c + a4.y * sk,
                           x4.z * c + a4.z * sk, x4.w * c + a4.w * sk);
    float s = z.x + z.y + z.z + z.w;
#pragma unroll
    for (int o = 16; o > 0; o >>= 1) s += __shfl_xor_sync(0xffffffffu, s, o);
    float mu = s * (1.0f / DD);
    float dx = z.x - mu, dy = z.y - mu, dz = z.z - mu, dw = z.w - mu;
    float vs = dx * dx + dy * dy + dz * dz + dw * dw;
#pragma unroll
    for (int o = 16; o > 0; o >>= 1) vs += __shfl_xor_sync(0xffffffffu, vs, o);
    float inv = rsqrtf(vs * (1.0f / DD) + EPSV);
    float4 g4 = ((const float4*)gg)[lane];
    float4 b4 = ((const float4*)bb)[lane];
    ((float4*)(xout + (size_t)node * DD))[lane] =
        make_float4(dx * inv * g4.x + b4.x, dy * inv * g4.y + b4.y,
                    dz * inv * g4.z + b4.z, dw * inv * g4.w + b4.w);
}

// ---------------- layer aggregation + final layernorm ----------------
__global__ void final_kernel(const float* __restrict__ aw, const float* __restrict__ gg,
                             const float* __restrict__ bb, float* __restrict__ out)
{
    int node = (blockIdx.x * blockDim.x + threadIdx.x) >> 5;
    int lane = threadIdx.x & 31;
    if (node >= NN) return;
    float a0 = __ldg(aw), a1 = __ldg(aw + 1);
    float mw = fmaxf(a0, a1);
    float e0 = expf(a0 - mw), e1 = expf(a1 - mw);
    float den = e0 + e1;
    float w0 = e0 / den, w1 = e1 / den;
    float4 x0 = ((const float4*)(g_o0 + (size_t)node * DD))[lane];
    float4 x1 = ((const float4*)(g_o1 + (size_t)node * DD))[lane];
    float4 z = make_float4(w0 * x0.x + w1 * x1.x, w0 * x0.y + w1 * x1.y,
                           w0 * x0.z + w1 * x1.z, w0 * x0.w + w1 * x1.w);
    float s = z.x + z.y + z.z + z.w;
#pragma unroll
    for (int o = 16; o > 0; o >>= 1) s += __shfl_xor_sync(0xffffffffu, s, o);
    float mu = s * (1.0f / DD);
    float dx = z.x - mu, dy = z.y - mu, dz = z.z - mu, dw = z.w - mu;
    float vs = dx * dx + dy * dy + dz * dz + dw * dw;
#pragma unroll
    for (int o = 16; o > 0; o >>= 1) vs += __shfl_xor_sync(0xffffffffu, vs, o);
    float inv = rsqrtf(vs * (1.0f / DD) + EPSV);
    float4 g4 = ((const float4*)gg)[lane];
    float4 b4 = ((const float4*)bb)[lane];
    ((float4*)(out + (size_t)node * DD))[lane] =
        make_float4(dx * inv * g4.x + b4.x, dy * inv * g4.y + b4.y,
                    dz * inv * g4.z + b4.z, dw * inv * g4.w + b4.w);
}

// ---------------- launch ----------------
extern "C" void kernel_launch(void* const* d_in, const int* in_sizes, int n_in,
                              void* d_out, int out_size)
{
    (void)in_sizes; (void)n_in; (void)out_size;
    const float* h    = (const float*)d_in[0];
    const int*   src  = (const int*)d_in[1];
    const int*   dst  = (const int*)d_in[2];
    const int*   ntyp = (const int*)d_in[3];
    const int*   etyp = (const int*)d_in[4];
    const float* Wk   = (const float*)d_in[5];
    const float* Wq   = (const float*)d_in[6];
    const float* Wv   = (const float*)d_in[7];
    const float* Wa   = (const float*)d_in[8];
    const float* Watt = (const float*)d_in[9];
    const float* Wmsg = (const float*)d_in[10];
    const float* pri  = (const float*)d_in[11];
    const float* skip = (const float*)d_in[12];
    const float* lng  = (const float*)d_in[13];
    const float* lnb  = (const float*)d_in[14];
    const float* aggw = (const float*)d_in[15];
    const float* aggg = (const float*)d_in[16];
    const float* aggb = (const float*)d_in[17];

    const size_t WS = (size_t)TT * DD * DD;
    const size_t ES = (size_t)HH * RR * DHh * DHh;
    const int TL_GRID = (NN + 63) / 64;
    const int NODE_GRID = (NN + 7) / 8;
    const int INIT_GRID = (NN * DD / 4 + 255) / 256;

    for (int l = 0; l < LLn; ++l) {
        int in_sel = (l == 0) ? 0 : 2;
        int ln_out = (l == 0) ? 0 : 1;
        init_kernel<<<INIT_GRID, 256>>>();
        typed_linear_kernel<3><<<TL_GRID, 256>>>(h, in_sel, ntyp,
                                                 Wk + l * WS, Wq + l * WS, Wv + l * WS);
        edge_fused_kernel<<<EDGE_GRID, 256>>>(src, dst, etyp,
                                              Watt + l * ES, Wmsg + l * ES,
                                              pri + l * HH * RR);
        typed_linear_kernel<1><<<TL_GRID, 256>>>(h, 1, ntyp,
                                                 Wa + l * WS, Wa + l * WS, Wa + l * WS);
        fuse_ln_kernel<<<NODE_GRID, 256>>>(h, in_sel, ntyp, skip + l * TT,
                                           lng + l * DD, lnb + l * DD, ln_out);
    }
    final_kernel<<<NODE_GRID, 256>>>(aggw, aggg, aggb, (float*)d_out);
}